// round 5
// baseline (speedup 1.0000x reference)
#include <cuda_runtime.h>
#include <cuda_fp16.h>

#define NN 100000
#define EE 1600000
#define MAXDEG 64

// ---------------- scratch (device globals: no allocation allowed) ----------------
__device__ __half2 g_h1h[NN * 32];  // layer-1 features, fp16 pairs (x @ W1)
__device__ __half2 g_h2h[NN * 32];  // layer-2 features, fp16 pairs
__device__ float g_als1[NN * 8];    // per-node per-head attn (src side), fp32
__device__ float g_ald1[NN * 8];    // per-node per-head attn (dst side), fp32
__device__ float g_agg1[NN * 64];   // layer-1 output: elu(agg + b1), fp32 (gemm2 input)
__device__ float g_als2[NN];
__device__ float g_ald2[NN];
__device__ int   g_cnt[NN];         // per-dst in-degree counters
__device__ int   g_ell[NN * MAXDEG];// padded per-dst src lists

__device__ __forceinline__ float lrelu(float x) { return x > 0.f ? x : 0.2f * x; }
__device__ __forceinline__ float eluf(float x)  { return x > 0.f ? x : expm1f(x); }

// ---------------- ELL build ----------------
__global__ void zero_cnt_kernel() {
    int n = blockIdx.x * 256 + threadIdx.x;
    if (n < NN) g_cnt[n] = 0;
}

__global__ void build_ell_kernel(const int* __restrict__ ei) {
    int e = blockIdx.x * 256 + threadIdx.x;
    if (e >= EE) return;
    int s = __ldg(ei + e), d = __ldg(ei + EE + e);
    int p = atomicAdd(g_cnt + d, 1);
    if (p < MAXDEG) g_ell[d * MAXDEG + p] = s;
}

// pack 8 fp32 -> uint4 of halves
__device__ __forceinline__ uint4 pack8h(const float* a) {
    __half2 h0 = __floats2half2_rn(a[0], a[1]);
    __half2 h1 = __floats2half2_rn(a[2], a[3]);
    __half2 h2 = __floats2half2_rn(a[4], a[5]);
    __half2 h3 = __floats2half2_rn(a[6], a[7]);
    uint4 r;
    r.x = *(unsigned*)&h0; r.y = *(unsigned*)&h1;
    r.z = *(unsigned*)&h2; r.w = *(unsigned*)&h3;
    return r;
}

// ---------------- GEMM 1 + fused al1:  h1 = x @ W1, logits from fp32 acc ----------------
// Thread (t) owns nodes ni..ni+7, cols ji..ji+7 where ji = one full head.
__global__ __launch_bounds__(128) void gemm1_kernel(const float* __restrict__ x,
                                                    const float* __restrict__ W,
                                                    const float* __restrict__ a_src,
                                                    const float* __restrict__ a_dst) {
    __shared__ float Xs[32 * 132];
    __shared__ float Ws[32 * 64];
    const int n0 = blockIdx.x * 128;
    const int t  = threadIdx.x;
    float acc[8][8];
#pragma unroll
    for (int i = 0; i < 8; i++)
#pragma unroll
        for (int j = 0; j < 8; j++) acc[i][j] = 0.f;
    const int ni = (t & 15) * 8;
    const int ji = (t >> 4) * 8;
    const int h  = t >> 4;          // head index of this thread's columns

    for (int kc = 0; kc < 128; kc += 32) {
        __syncthreads();
#pragma unroll
        for (int i = 0; i < 8; i++) {
            int idx = t + i * 128;
            int k4  = idx & 7;
            int n   = idx >> 3;
            int node = n0 + n;
            float4 v = make_float4(0.f, 0.f, 0.f, 0.f);
            if (node < NN) v = __ldg((const float4*)x + node * 32 + (kc >> 2) + k4);
            Xs[(k4 * 4 + 0) * 132 + n] = v.x;
            Xs[(k4 * 4 + 1) * 132 + n] = v.y;
            Xs[(k4 * 4 + 2) * 132 + n] = v.z;
            Xs[(k4 * 4 + 3) * 132 + n] = v.w;
        }
#pragma unroll
        for (int i = 0; i < 4; i++) {
            int idx = t + i * 128;
            ((float4*)Ws)[idx] = __ldg((const float4*)W + kc * 16 + idx);
        }
        __syncthreads();
#pragma unroll
        for (int k = 0; k < 32; k++) {
            const float4 a0 = *(const float4*)(Xs + k * 132 + ni);
            const float4 a1 = *(const float4*)(Xs + k * 132 + ni + 4);
            const float4 b0 = *(const float4*)(Ws + k * 64 + ji);
            const float4 b1 = *(const float4*)(Ws + k * 64 + ji + 4);
            float av[8] = {a0.x, a0.y, a0.z, a0.w, a1.x, a1.y, a1.z, a1.w};
            float bv[8] = {b0.x, b0.y, b0.z, b0.w, b1.x, b1.y, b1.z, b1.w};
#pragma unroll
            for (int i = 0; i < 8; i++)
#pragma unroll
                for (int j = 0; j < 8; j++) acc[i][j] = fmaf(av[i], bv[j], acc[i][j]);
        }
    }
    const float4 s0 = __ldg((const float4*)a_src + h * 2);
    const float4 s1 = __ldg((const float4*)a_src + h * 2 + 1);
    const float4 d0 = __ldg((const float4*)a_dst + h * 2);
    const float4 d1 = __ldg((const float4*)a_dst + h * 2 + 1);
#pragma unroll
    for (int i = 0; i < 8; i++) {
        int node = n0 + ni + i;
        if (node < NN) {
            *(uint4*)(g_h1h + node * 32 + (ji >> 1)) = pack8h(acc[i]);
            float s = acc[i][0] * s0.x + acc[i][1] * s0.y + acc[i][2] * s0.z + acc[i][3] * s0.w
                    + acc[i][4] * s1.x + acc[i][5] * s1.y + acc[i][6] * s1.z + acc[i][7] * s1.w;
            float d = acc[i][0] * d0.x + acc[i][1] * d0.y + acc[i][2] * d0.z + acc[i][3] * d0.w
                    + acc[i][4] * d1.x + acc[i][5] * d1.y + acc[i][6] * d1.z + acc[i][7] * d1.w;
            g_als1[node * 8 + h] = s;
            g_ald1[node * 8 + h] = d;
        }
    }
}

// ---------------- GEMM 2 + fused al2: h2 = agg1 @ W2, logit partials reduced in smem ----------------
__global__ __launch_bounds__(128) void gemm2_kernel(const float* __restrict__ W,
                                                    const float* __restrict__ a_src,
                                                    const float* __restrict__ a_dst) {
    __shared__ float Xs[32 * 132];
    __shared__ float Ws[32 * 64];
    const int n0 = blockIdx.x * 128;
    const int t  = threadIdx.x;
    float acc[8][8];
#pragma unroll
    for (int i = 0; i < 8; i++)
#pragma unroll
        for (int j = 0; j < 8; j++) acc[i][j] = 0.f;
    const int ni = (t & 15) * 8;
    const int ji = (t >> 4) * 8;

    for (int kc = 0; kc < 64; kc += 32) {
        __syncthreads();
#pragma unroll
        for (int i = 0; i < 8; i++) {
            int idx = t + i * 128;
            int k4  = idx & 7;
            int n   = idx >> 3;
            int node = n0 + n;
            float4 v = make_float4(0.f, 0.f, 0.f, 0.f);
            if (node < NN) v = __ldg((const float4*)g_agg1 + node * 16 + (kc >> 2) + k4);
            Xs[(k4 * 4 + 0) * 132 + n] = v.x;
            Xs[(k4 * 4 + 1) * 132 + n] = v.y;
            Xs[(k4 * 4 + 2) * 132 + n] = v.z;
            Xs[(k4 * 4 + 3) * 132 + n] = v.w;
        }
#pragma unroll
        for (int i = 0; i < 4; i++) {
            int idx = t + i * 128;
            ((float4*)Ws)[idx] = __ldg((const float4*)W + kc * 16 + idx);
        }
        __syncthreads();
#pragma unroll
        for (int k = 0; k < 32; k++) {
            const float4 a0 = *(const float4*)(Xs + k * 132 + ni);
            const float4 a1 = *(const float4*)(Xs + k * 132 + ni + 4);
            const float4 b0 = *(const float4*)(Ws + k * 64 + ji);
            const float4 b1 = *(const float4*)(Ws + k * 64 + ji + 4);
            float av[8] = {a0.x, a0.y, a0.z, a0.w, a1.x, a1.y, a1.z, a1.w};
            float bv[8] = {b0.x, b0.y, b0.z, b0.w, b1.x, b1.y, b1.z, b1.w};
#pragma unroll
            for (int i = 0; i < 8; i++)
#pragma unroll
                for (int j = 0; j < 8; j++) acc[i][j] = fmaf(av[i], bv[j], acc[i][j]);
        }
    }
    // partial attn dots over this thread's 8 columns
    const float4 s0 = __ldg((const float4*)a_src + (ji >> 2));
    const float4 s1 = __ldg((const float4*)a_src + (ji >> 2) + 1);
    const float4 d0 = __ldg((const float4*)a_dst + (ji >> 2));
    const float4 d1 = __ldg((const float4*)a_dst + (ji >> 2) + 1);
    float sp[8], dp[8];
#pragma unroll
    for (int i = 0; i < 8; i++) {
        int node = n0 + ni + i;
        if (node < NN)
            *(uint4*)(g_h2h + node * 32 + (ji >> 1)) = pack8h(acc[i]);
        sp[i] = acc[i][0] * s0.x + acc[i][1] * s0.y + acc[i][2] * s0.z + acc[i][3] * s0.w
              + acc[i][4] * s1.x + acc[i][5] * s1.y + acc[i][6] * s1.z + acc[i][7] * s1.w;
        dp[i] = acc[i][0] * d0.x + acc[i][1] * d0.y + acc[i][2] * d0.z + acc[i][3] * d0.w
              + acc[i][4] * d1.x + acc[i][5] * d1.y + acc[i][6] * d1.z + acc[i][7] * d1.w;
    }
    // reduce the 8 column-group partials per node via smem (reuse Xs/Ws region)
    __syncthreads();
    float* redS = Xs;          // [8][128]
    float* redD = Xs + 1024;   // [8][128]
    const int g = t >> 4;
#pragma unroll
    for (int i = 0; i < 8; i++) {
        redS[g * 128 + ni + i] = sp[i];
        redD[g * 128 + ni + i] = dp[i];
    }
    __syncthreads();
    int node = n0 + t;
    if (node < NN) {
        float s = 0.f, d = 0.f;
#pragma unroll
        for (int gg = 0; gg < 8; gg++) {
            s += redS[gg * 128 + t];
            d += redD[gg * 128 + t];
        }
        g_als2[node] = s;
        g_ald2[node] = d;
    }
}

// ---------------- fused den+agg layer 1: TWO dsts per warp (double MLP) ----------------
__global__ __launch_bounds__(256) void agg1_kernel(const float* __restrict__ b1) {
    int gw = (blockIdx.x * 256 + threadIdx.x) >> 5;   // global warp id
    int l  = threadIdx.x & 31;
    int dA = gw * 2, dB = dA + 1;
    if (dA >= NN) return;
    const bool hasB = dB < NN;
    const int h0 = l >> 2;

    float aldA = g_ald1[dA * 8 + h0];
    float wA = __expf(lrelu(g_als1[dA * 8 + h0] + aldA));
    float2 hvA = __half22float2(g_h1h[dA * 32 + l]);
    float accA0 = wA * hvA.x, accA1 = wA * hvA.y, denA = wA;
    int degA = min(g_cnt[dA], MAXDEG);

    float aldB = 0.f, accB0 = 0.f, accB1 = 0.f, denB = 1.f;
    int degB = 0;
    if (hasB) {
        aldB = g_ald1[dB * 8 + h0];
        float wB = __expf(lrelu(g_als1[dB * 8 + h0] + aldB));
        float2 hvB = __half22float2(g_h1h[dB * 32 + l]);
        accB0 = wB * hvB.x; accB1 = wB * hvB.y; denB = wB;
        degB = min(g_cnt[dB], MAXDEG);
    }

    int iA0 = (l      < degA) ? g_ell[dA * MAXDEG + l]      : 0;
    int iA1 = (l + 32 < degA) ? g_ell[dA * MAXDEG + l + 32] : 0;
    int iB0 = (l      < degB) ? g_ell[dB * MAXDEG + l]      : 0;
    int iB1 = (l + 32 < degB) ? g_ell[dB * MAXDEG + l + 32] : 0;

    int m = max(degA, degB);
#pragma unroll 4
    for (int e = 0; e < m; e++) {
        int sA = __shfl_sync(0xffffffffu, (e < 32) ? iA0 : iA1, e & 31);
        int sB = __shfl_sync(0xffffffffu, (e < 32) ? iB0 : iB1, e & 31);
        if (e < degA) {
            float a = g_als1[sA * 8 + h0];
            float2 v = __half22float2(g_h1h[sA * 32 + l]);
            float ew = __expf(lrelu(a + aldA));
            accA0 = fmaf(ew, v.x, accA0);
            accA1 = fmaf(ew, v.y, accA1);
            denA += ew;
        }
        if (e < degB) {
            float a = g_als1[sB * 8 + h0];
            float2 v = __half22float2(g_h1h[sB * 32 + l]);
            float ew = __expf(lrelu(a + aldB));
            accB0 = fmaf(ew, v.x, accB0);
            accB1 = fmaf(ew, v.y, accB1);
            denB += ew;
        }
    }
    float bb0 = __ldg(b1 + 2 * l), bb1 = __ldg(b1 + 2 * l + 1);
    float invA = 1.f / denA;
    *(float2*)(g_agg1 + dA * 64 + 2 * l) =
        make_float2(eluf(accA0 * invA + bb0), eluf(accA1 * invA + bb1));
    if (hasB) {
        float invB = 1.f / denB;
        *(float2*)(g_agg1 + dB * 64 + 2 * l) =
            make_float2(eluf(accB0 * invB + bb0), eluf(accB1 * invB + bb1));
    }
}

// ---------------- fused den+agg layer 2: TWO dsts per warp ----------------
__global__ __launch_bounds__(256) void agg2_kernel(const float* __restrict__ b2,
                                                   float* __restrict__ out) {
    int gw = (blockIdx.x * 256 + threadIdx.x) >> 5;
    int l  = threadIdx.x & 31;
    int dA = gw * 2, dB = dA + 1;
    if (dA >= NN) return;
    const bool hasB = dB < NN;

    float aldA = g_ald2[dA];
    float wA = __expf(lrelu(g_als2[dA] + aldA));
    float2 hvA = __half22float2(g_h2h[dA * 32 + l]);
    float accA0 = wA * hvA.x, accA1 = wA * hvA.y, denA = wA;
    int degA = min(g_cnt[dA], MAXDEG);

    float aldB = 0.f, accB0 = 0.f, accB1 = 0.f, denB = 1.f;
    int degB = 0;
    if (hasB) {
        aldB = g_ald2[dB];
        float wB = __expf(lrelu(g_als2[dB] + aldB));
        float2 hvB = __half22float2(g_h2h[dB * 32 + l]);
        accB0 = wB * hvB.x; accB1 = wB * hvB.y; denB = wB;
        degB = min(g_cnt[dB], MAXDEG);
    }

    int iA0 = (l      < degA) ? g_ell[dA * MAXDEG + l]      : 0;
    int iA1 = (l + 32 < degA) ? g_ell[dA * MAXDEG + l + 32] : 0;
    int iB0 = (l      < degB) ? g_ell[dB * MAXDEG + l]      : 0;
    int iB1 = (l + 32 < degB) ? g_ell[dB * MAXDEG + l + 32] : 0;

    int m = max(degA, degB);
#pragma unroll 4
    for (int e = 0; e < m; e++) {
        int sA = __shfl_sync(0xffffffffu, (e < 32) ? iA0 : iA1, e & 31);
        int sB = __shfl_sync(0xffffffffu, (e < 32) ? iB0 : iB1, e & 31);
        if (e < degA) {
            float a = g_als2[sA];
            float2 v = __half22float2(g_h2h[sA * 32 + l]);
            float ew = __expf(lrelu(a + aldA));
            accA0 = fmaf(ew, v.x, accA0);
            accA1 = fmaf(ew, v.y, accA1);
            denA += ew;
        }
        if (e < degB) {
            float a = g_als2[sB];
            float2 v = __half22float2(g_h2h[sB * 32 + l]);
            float ew = __expf(lrelu(a + aldB));
            accB0 = fmaf(ew, v.x, accB0);
            accB1 = fmaf(ew, v.y, accB1);
            denB += ew;
        }
    }
    float bb0 = __ldg(b2 + 2 * l), bb1 = __ldg(b2 + 2 * l + 1);
    float invA = 1.f / denA;
    *(float2*)(out + dA * 64 + 2 * l) =
        make_float2(accA0 * invA + bb0, accA1 * invA + bb1);
    if (hasB) {
        float invB = 1.f / denB;
        *(float2*)(out + dB * 64 + 2 * l) =
            make_float2(accB0 * invB + bb0, accB1 * invB + bb1);
    }
}

// ---------------- launch ----------------
extern "C" void kernel_launch(void* const* d_in, const int* in_sizes, int n_in,
                              void* d_out, int out_size) {
    const float* x   = (const float*)d_in[0];
    const int*   ei  = (const int*)d_in[1];
    const float* W1  = (const float*)d_in[2];
    const float* as1 = (const float*)d_in[3];
    const float* ad1 = (const float*)d_in[4];
    const float* b1  = (const float*)d_in[5];
    const float* W2  = (const float*)d_in[6];
    const float* as2 = (const float*)d_in[7];
    const float* ad2 = (const float*)d_in[8];
    const float* b2  = (const float*)d_in[9];
    float* out = (float*)d_out;

    const int GB = (NN + 127) / 128;
    const int AGGB = ((NN + 1) / 2 + 7) / 8;   // 2 dsts/warp, 8 warps/block

    zero_cnt_kernel<<<(NN + 255) / 256, 256>>>();
    build_ell_kernel<<<(EE + 255) / 256, 256>>>(ei);
    gemm1_kernel<<<GB, 128>>>(x, W1, as1, ad1);
    agg1_kernel<<<AGGB, 256>>>(b1);
    gemm2_kernel<<<GB, 128>>>(W2, as2, ad2);
    agg2_kernel<<<AGGB, 256>>>(b2, out);
}

// round 7
// speedup vs baseline: 1.2066x; 1.2066x over previous
#include <cuda_runtime.h>
#include <cuda_fp16.h>

#define NN 100000
#define EE 1600000
#define MAXDEG 64

// ---------------- scratch (device globals: no allocation allowed) ----------------
__device__ __half2 g_h1h[NN * 32];  // layer-1 features, fp16 pairs (x @ W1)
__device__ __half2 g_h2h[NN * 32];  // layer-2 features, fp16 pairs
__device__ float g_als1[NN * 8];    // per-node per-head attn (src side), fp32
__device__ float g_ald1[NN * 8];    // per-node per-head attn (dst side), fp32
__device__ float g_agg1[NN * 64];   // layer-1 output: elu(agg + b1), fp32 (gemm2 input)
__device__ float g_als2[NN];
__device__ float g_ald2[NN];
__device__ int   g_cnt[NN];         // per-dst in-degree counters
__device__ int   g_ell[NN * MAXDEG];// padded per-dst src lists

__device__ __forceinline__ float eluf(float x)  { return x > 0.f ? x : expm1f(x); }

// ---------------- ELL build ----------------
__global__ void zero_cnt_kernel() {
    int n = blockIdx.x * 256 + threadIdx.x;
    if (n < NN) g_cnt[n] = 0;
}

__global__ void build_ell_kernel(const int* __restrict__ ei) {
    int e = blockIdx.x * 256 + threadIdx.x;
    if (e >= EE) return;
    int s = __ldg(ei + e), d = __ldg(ei + EE + e);
    int p = atomicAdd(g_cnt + d, 1);
    if (p < MAXDEG) g_ell[d * MAXDEG + p] = s;
}

// pack 8 fp32 -> uint4 of halves
__device__ __forceinline__ uint4 pack8h(const float* a) {
    __half2 h0 = __floats2half2_rn(a[0], a[1]);
    __half2 h1 = __floats2half2_rn(a[2], a[3]);
    __half2 h2 = __floats2half2_rn(a[4], a[5]);
    __half2 h3 = __floats2half2_rn(a[6], a[7]);
    uint4 r;
    r.x = *(unsigned*)&h0; r.y = *(unsigned*)&h1;
    r.z = *(unsigned*)&h2; r.w = *(unsigned*)&h3;
    return r;
}

// ---------------- GEMM 1 + fused al1:  h1 = x @ W1, logits from fp32 acc ----------------
__global__ __launch_bounds__(128) void gemm1_kernel(const float* __restrict__ x,
                                                    const float* __restrict__ W,
                                                    const float* __restrict__ a_src,
                                                    const float* __restrict__ a_dst) {
    __shared__ float Xs[32 * 132];
    __shared__ float Ws[32 * 64];
    const int n0 = blockIdx.x * 128;
    const int t  = threadIdx.x;
    float acc[8][8];
#pragma unroll
    for (int i = 0; i < 8; i++)
#pragma unroll
        for (int j = 0; j < 8; j++) acc[i][j] = 0.f;
    const int ni = (t & 15) * 8;
    const int ji = (t >> 4) * 8;
    const int h  = t >> 4;

    for (int kc = 0; kc < 128; kc += 32) {
        __syncthreads();
#pragma unroll
        for (int i = 0; i < 8; i++) {
            int idx = t + i * 128;
            int k4  = idx & 7;
            int n   = idx >> 3;
            int node = n0 + n;
            float4 v = make_float4(0.f, 0.f, 0.f, 0.f);
            if (node < NN) v = __ldg((const float4*)x + node * 32 + (kc >> 2) + k4);
            Xs[(k4 * 4 + 0) * 132 + n] = v.x;
            Xs[(k4 * 4 + 1) * 132 + n] = v.y;
            Xs[(k4 * 4 + 2) * 132 + n] = v.z;
            Xs[(k4 * 4 + 3) * 132 + n] = v.w;
        }
#pragma unroll
        for (int i = 0; i < 4; i++) {
            int idx = t + i * 128;
            ((float4*)Ws)[idx] = __ldg((const float4*)W + kc * 16 + idx);
        }
        __syncthreads();
#pragma unroll
        for (int k = 0; k < 32; k++) {
            const float4 a0 = *(const float4*)(Xs + k * 132 + ni);
            const float4 a1 = *(const float4*)(Xs + k * 132 + ni + 4);
            const float4 b0 = *(const float4*)(Ws + k * 64 + ji);
            const float4 b1 = *(const float4*)(Ws + k * 64 + ji + 4);
            float av[8] = {a0.x, a0.y, a0.z, a0.w, a1.x, a1.y, a1.z, a1.w};
            float bv[8] = {b0.x, b0.y, b0.z, b0.w, b1.x, b1.y, b1.z, b1.w};
#pragma unroll
            for (int i = 0; i < 8; i++)
#pragma unroll
                for (int j = 0; j < 8; j++) acc[i][j] = fmaf(av[i], bv[j], acc[i][j]);
        }
    }
    const float4 s0 = __ldg((const float4*)a_src + h * 2);
    const float4 s1 = __ldg((const float4*)a_src + h * 2 + 1);
    const float4 d0 = __ldg((const float4*)a_dst + h * 2);
    const float4 d1 = __ldg((const float4*)a_dst + h * 2 + 1);
#pragma unroll
    for (int i = 0; i < 8; i++) {
        int node = n0 + ni + i;
        if (node < NN) {
            *(uint4*)(g_h1h + node * 32 + (ji >> 1)) = pack8h(acc[i]);
            float s = acc[i][0] * s0.x + acc[i][1] * s0.y + acc[i][2] * s0.z + acc[i][3] * s0.w
                    + acc[i][4] * s1.x + acc[i][5] * s1.y + acc[i][6] * s1.z + acc[i][7] * s1.w;
            float d = acc[i][0] * d0.x + acc[i][1] * d0.y + acc[i][2] * d0.z + acc[i][3] * d0.w
                    + acc[i][4] * d1.x + acc[i][5] * d1.y + acc[i][6] * d1.z + acc[i][7] * d1.w;
            g_als1[node * 8 + h] = s;
            g_ald1[node * 8 + h] = d;
        }
    }
}

// ---------------- GEMM 2 + fused al2: h2 = agg1 @ W2, logit partials reduced in smem ----------------
__global__ __launch_bounds__(128) void gemm2_kernel(const float* __restrict__ W,
                                                    const float* __restrict__ a_src,
                                                    const float* __restrict__ a_dst) {
    __shared__ float Xs[32 * 132];
    __shared__ float Ws[32 * 64];
    const int n0 = blockIdx.x * 128;
    const int t  = threadIdx.x;
    float acc[8][8];
#pragma unroll
    for (int i = 0; i < 8; i++)
#pragma unroll
        for (int j = 0; j < 8; j++) acc[i][j] = 0.f;
    const int ni = (t & 15) * 8;
    const int ji = (t >> 4) * 8;

    for (int kc = 0; kc < 64; kc += 32) {
        __syncthreads();
#pragma unroll
        for (int i = 0; i < 8; i++) {
            int idx = t + i * 128;
            int k4  = idx & 7;
            int n   = idx >> 3;
            int node = n0 + n;
            float4 v = make_float4(0.f, 0.f, 0.f, 0.f);
            if (node < NN) v = __ldg((const float4*)g_agg1 + node * 16 + (kc >> 2) + k4);
            Xs[(k4 * 4 + 0) * 132 + n] = v.x;
            Xs[(k4 * 4 + 1) * 132 + n] = v.y;
            Xs[(k4 * 4 + 2) * 132 + n] = v.z;
            Xs[(k4 * 4 + 3) * 132 + n] = v.w;
        }
#pragma unroll
        for (int i = 0; i < 4; i++) {
            int idx = t + i * 128;
            ((float4*)Ws)[idx] = __ldg((const float4*)W + kc * 16 + idx);
        }
        __syncthreads();
#pragma unroll
        for (int k = 0; k < 32; k++) {
            const float4 a0 = *(const float4*)(Xs + k * 132 + ni);
            const float4 a1 = *(const float4*)(Xs + k * 132 + ni + 4);
            const float4 b0 = *(const float4*)(Ws + k * 64 + ji);
            const float4 b1 = *(const float4*)(Ws + k * 64 + ji + 4);
            float av[8] = {a0.x, a0.y, a0.z, a0.w, a1.x, a1.y, a1.z, a1.w};
            float bv[8] = {b0.x, b0.y, b0.z, b0.w, b1.x, b1.y, b1.z, b1.w};
#pragma unroll
            for (int i = 0; i < 8; i++)
#pragma unroll
                for (int j = 0; j < 8; j++) acc[i][j] = fmaf(av[i], bv[j], acc[i][j]);
        }
    }
    const float4 s0 = __ldg((const float4*)a_src + (ji >> 2));
    const float4 s1 = __ldg((const float4*)a_src + (ji >> 2) + 1);
    const float4 d0 = __ldg((const float4*)a_dst + (ji >> 2));
    const float4 d1 = __ldg((const float4*)a_dst + (ji >> 2) + 1);
    float sp[8], dp[8];
#pragma unroll
    for (int i = 0; i < 8; i++) {
        int node = n0 + ni + i;
        if (node < NN)
            *(uint4*)(g_h2h + node * 32 + (ji >> 1)) = pack8h(acc[i]);
        sp[i] = acc[i][0] * s0.x + acc[i][1] * s0.y + acc[i][2] * s0.z + acc[i][3] * s0.w
              + acc[i][4] * s1.x + acc[i][5] * s1.y + acc[i][6] * s1.z + acc[i][7] * s1.w;
        dp[i] = acc[i][0] * d0.x + acc[i][1] * d0.y + acc[i][2] * d0.z + acc[i][3] * d0.w
              + acc[i][4] * d1.x + acc[i][5] * d1.y + acc[i][6] * d1.z + acc[i][7] * d1.w;
    }
    __syncthreads();
    float* redS = Xs;          // [8][128]
    float* redD = Xs + 1024;   // [8][128]
    const int g = t >> 4;
#pragma unroll
    for (int i = 0; i < 8; i++) {
        redS[g * 128 + ni + i] = sp[i];
        redD[g * 128 + ni + i] = dp[i];
    }
    __syncthreads();
    int node = n0 + t;
    if (node < NN) {
        float s = 0.f, d = 0.f;
#pragma unroll
        for (int gg = 0; gg < 8; gg++) {
            s += redS[gg * 128 + t];
            d += redD[gg * 128 + t];
        }
        g_als2[node] = s;
        g_ald2[node] = d;
    }
}

// ---------------- fused den+agg layer 1: HALF-WARP per dst, 4 ch/lane ----------------
// exp(lrelu(x)) = ex2(max(t, 0.2t)), t = x*log2(e)
__global__ __launch_bounds__(256) void agg1_kernel(const float* __restrict__ b1) {
    const int gw = (blockIdx.x * 256 + threadIdx.x) >> 5;  // global warp id
    const int l  = threadIdx.x & 31;
    const int c  = l & 15;                 // channel group: channels 4c..4c+3
    const int d  = gw * 2 + (l >> 4);      // dst for this half-warp (NN even -> always valid)
    const int h  = c >> 1;                 // head of channels 4c..4c+3
    const float L2E = 1.44269504f;

    const float ald = g_ald1[d * 8 + h] * L2E;
    // self loop
    float t0 = fmaf(g_als1[d * 8 + h], L2E, ald);
    float w  = exp2f(fmaxf(t0, 0.2f * t0));
    uint2 rs = *(const uint2*)(g_h1h + d * 32 + c * 2);
    float2 v0 = __half22float2(*(__half2*)&rs.x);
    float2 v1 = __half22float2(*(__half2*)&rs.y);
    float a0 = w * v0.x, a1 = w * v0.y, a2 = w * v1.x, a3 = w * v1.y, den = w;

    const int deg = min(g_cnt[d], MAXDEG);
    const int m = max(deg, __shfl_xor_sync(0xffffffffu, deg, 16));
    const int* __restrict__ ell = g_ell + d * MAXDEG;

#pragma unroll 4
    for (int e = 0; e < m; e++) {
        if (e < deg) {
            int s = __ldg(ell + e);                       // broadcast within half-warp
            float as = __ldg(g_als1 + s * 8 + h);
            float tt = fmaf(as, L2E, ald);
            float ew = exp2f(fmaxf(tt, 0.2f * tt));
            uint2 r = __ldg((const uint2*)(g_h1h + s * 32 + c * 2));
            float2 u0 = __half22float2(*(__half2*)&r.x);
            float2 u1 = __half22float2(*(__half2*)&r.y);
            a0 = fmaf(ew, u0.x, a0);
            a1 = fmaf(ew, u0.y, a1);
            a2 = fmaf(ew, u1.x, a2);
            a3 = fmaf(ew, u1.y, a3);
            den += ew;
        }
    }
    float inv = 1.f / den;
    float4 bb = __ldg((const float4*)b1 + c);
    float4 r;
    r.x = eluf(fmaf(a0, inv, bb.x));
    r.y = eluf(fmaf(a1, inv, bb.y));
    r.z = eluf(fmaf(a2, inv, bb.z));
    r.w = eluf(fmaf(a3, inv, bb.w));
    *(float4*)(g_agg1 + d * 64 + c * 4) = r;
}

// ---------------- fused den+agg layer 2: HALF-WARP per dst, 4 ch/lane ----------------
__global__ __launch_bounds__(256) void agg2_kernel(const float* __restrict__ b2,
                                                   float* __restrict__ out) {
    const int gw = (blockIdx.x * 256 + threadIdx.x) >> 5;
    const int l  = threadIdx.x & 31;
    const int c  = l & 15;
    const int d  = gw * 2 + (l >> 4);
    const float L2E = 1.44269504f;

    const float ald = g_ald2[d] * L2E;
    float t0 = fmaf(g_als2[d], L2E, ald);
    float w  = exp2f(fmaxf(t0, 0.2f * t0));
    uint2 rs = *(const uint2*)(g_h2h + d * 32 + c * 2);
    float2 v0 = __half22float2(*(__half2*)&rs.x);
    float2 v1 = __half22float2(*(__half2*)&rs.y);
    float a0 = w * v0.x, a1 = w * v0.y, a2 = w * v1.x, a3 = w * v1.y, den = w;

    const int deg = min(g_cnt[d], MAXDEG);
    const int m = max(deg, __shfl_xor_sync(0xffffffffu, deg, 16));
    const int* __restrict__ ell = g_ell + d * MAXDEG;

#pragma unroll 4
    for (int e = 0; e < m; e++) {
        if (e < deg) {
            int s = __ldg(ell + e);
            float as = __ldg(g_als2 + s);                 // broadcast within half-warp
            float tt = fmaf(as, L2E, ald);
            float ew = exp2f(fmaxf(tt, 0.2f * tt));
            uint2 r = __ldg((const uint2*)(g_h2h + s * 32 + c * 2));
            float2 u0 = __half22float2(*(__half2*)&r.x);
            float2 u1 = __half22float2(*(__half2*)&r.y);
            a0 = fmaf(ew, u0.x, a0);
            a1 = fmaf(ew, u0.y, a1);
            a2 = fmaf(ew, u1.x, a2);
            a3 = fmaf(ew, u1.y, a3);
            den += ew;
        }
    }
    float inv = 1.f / den;
    float4 bb = __ldg((const float4*)b2 + c);
    float4 r;
    r.x = fmaf(a0, inv, bb.x);
    r.y = fmaf(a1, inv, bb.y);
    r.z = fmaf(a2, inv, bb.z);
    r.w = fmaf(a3, inv, bb.w);
    *(float4*)(out + d * 64 + c * 4) = r;
}

// ---------------- launch ----------------
extern "C" void kernel_launch(void* const* d_in, const int* in_sizes, int n_in,
                              void* d_out, int out_size) {
    const float* x   = (const float*)d_in[0];
    const int*   ei  = (const int*)d_in[1];
    const float* W1  = (const float*)d_in[2];
    const float* as1 = (const float*)d_in[3];
    const float* ad1 = (const float*)d_in[4];
    const float* b1  = (const float*)d_in[5];
    const float* W2  = (const float*)d_in[6];
    const float* as2 = (const float*)d_in[7];
    const float* ad2 = (const float*)d_in[8];
    const float* b2  = (const float*)d_in[9];
    float* out = (float*)d_out;

    const int GB = (NN + 127) / 128;
    const int AGGB = NN / 16;           // 2 dsts per warp (half-warp each), 8 warps/block

    zero_cnt_kernel<<<(NN + 255) / 256, 256>>>();
    build_ell_kernel<<<(EE + 255) / 256, 256>>>(ei);
    gemm1_kernel<<<GB, 128>>>(x, W1, as1, ad1);
    agg1_kernel<<<AGGB, 256>>>(b1);
    gemm2_kernel<<<GB, 128>>>(W2, as2, ad2);
    agg2_kernel<<<AGGB, 256>>>(b2, out);
}

// round 8
// speedup vs baseline: 1.4382x; 1.1919x over previous
#include <cuda_runtime.h>
#include <cuda_fp16.h>

#define NN 100000
#define EE 1600000
#define MAXDEG 64

// ---------------- scratch (device globals; +1 sentinel row at index NN) ----------------
__device__ __half2 g_h1h[(NN + 1) * 32];  // layer-1 features, fp16 pairs
__device__ __half2 g_h2h[(NN + 1) * 32];  // layer-2 features, fp16 pairs
__device__ float g_als1[(NN + 1) * 8];    // src logits * log2(e); sentinel = -1e30
__device__ float g_ald1[NN * 8];          // dst logits * log2(e)
__device__ float g_agg1[NN * 64];         // layer-1 output: elu(agg + b1), fp32
__device__ float g_als2[NN + 1];
__device__ float g_ald2[NN];
__device__ int   g_cnt[NN];               // per-dst in-degree counters
__device__ int   g_ell[NN * MAXDEG];      // padded per-dst src lists

__device__ __forceinline__ float eluf(float x)  { return x > 0.f ? x : expm1f(x); }

// ---------------- init: counters + sentinel rows ----------------
__global__ void zero_cnt_kernel() {
    int n = blockIdx.x * 256 + threadIdx.x;
    if (n < NN) g_cnt[n] = 0;
    if (n < 32) {
        g_h1h[NN * 32 + n] = __floats2half2_rn(0.f, 0.f);
        g_h2h[NN * 32 + n] = __floats2half2_rn(0.f, 0.f);
    }
    if (n < 8) g_als1[NN * 8 + n] = -1e30f;
    if (n == 0) g_als2[NN] = -1e30f;
}

__global__ void build_ell_kernel(const int* __restrict__ ei) {
    int e = blockIdx.x * 256 + threadIdx.x;
    if (e >= EE) return;
    int s = __ldg(ei + e), d = __ldg(ei + EE + e);
    int p = atomicAdd(g_cnt + d, 1);
    if (p < MAXDEG) g_ell[d * MAXDEG + p] = s;
}

// pack 8 fp32 -> uint4 of halves
__device__ __forceinline__ uint4 pack8h(const float* a) {
    __half2 h0 = __floats2half2_rn(a[0], a[1]);
    __half2 h1 = __floats2half2_rn(a[2], a[3]);
    __half2 h2 = __floats2half2_rn(a[4], a[5]);
    __half2 h3 = __floats2half2_rn(a[6], a[7]);
    uint4 r;
    r.x = *(unsigned*)&h0; r.y = *(unsigned*)&h1;
    r.z = *(unsigned*)&h2; r.w = *(unsigned*)&h3;
    return r;
}

#define L2E 1.44269504f

// ---------------- GEMM 1 + fused al1 (logits pre-scaled by log2 e) ----------------
__global__ __launch_bounds__(128) void gemm1_kernel(const float* __restrict__ x,
                                                    const float* __restrict__ W,
                                                    const float* __restrict__ a_src,
                                                    const float* __restrict__ a_dst) {
    __shared__ float Xs[32 * 132];
    __shared__ float Ws[32 * 64];
    const int n0 = blockIdx.x * 128;
    const int t  = threadIdx.x;
    float acc[8][8];
#pragma unroll
    for (int i = 0; i < 8; i++)
#pragma unroll
        for (int j = 0; j < 8; j++) acc[i][j] = 0.f;
    const int ni = (t & 15) * 8;
    const int ji = (t >> 4) * 8;
    const int h  = t >> 4;

    for (int kc = 0; kc < 128; kc += 32) {
        __syncthreads();
#pragma unroll
        for (int i = 0; i < 8; i++) {
            int idx = t + i * 128;
            int k4  = idx & 7;
            int n   = idx >> 3;
            int node = n0 + n;
            float4 v = make_float4(0.f, 0.f, 0.f, 0.f);
            if (node < NN) v = __ldg((const float4*)x + node * 32 + (kc >> 2) + k4);
            Xs[(k4 * 4 + 0) * 132 + n] = v.x;
            Xs[(k4 * 4 + 1) * 132 + n] = v.y;
            Xs[(k4 * 4 + 2) * 132 + n] = v.z;
            Xs[(k4 * 4 + 3) * 132 + n] = v.w;
        }
#pragma unroll
        for (int i = 0; i < 4; i++) {
            int idx = t + i * 128;
            ((float4*)Ws)[idx] = __ldg((const float4*)W + kc * 16 + idx);
        }
        __syncthreads();
#pragma unroll
        for (int k = 0; k < 32; k++) {
            const float4 a0 = *(const float4*)(Xs + k * 132 + ni);
            const float4 a1 = *(const float4*)(Xs + k * 132 + ni + 4);
            const float4 b0 = *(const float4*)(Ws + k * 64 + ji);
            const float4 b1 = *(const float4*)(Ws + k * 64 + ji + 4);
            float av[8] = {a0.x, a0.y, a0.z, a0.w, a1.x, a1.y, a1.z, a1.w};
            float bv[8] = {b0.x, b0.y, b0.z, b0.w, b1.x, b1.y, b1.z, b1.w};
#pragma unroll
            for (int i = 0; i < 8; i++)
#pragma unroll
                for (int j = 0; j < 8; j++) acc[i][j] = fmaf(av[i], bv[j], acc[i][j]);
        }
    }
    const float4 s0 = __ldg((const float4*)a_src + h * 2);
    const float4 s1 = __ldg((const float4*)a_src + h * 2 + 1);
    const float4 d0 = __ldg((const float4*)a_dst + h * 2);
    const float4 d1 = __ldg((const float4*)a_dst + h * 2 + 1);
#pragma unroll
    for (int i = 0; i < 8; i++) {
        int node = n0 + ni + i;
        if (node < NN) {
            *(uint4*)(g_h1h + node * 32 + (ji >> 1)) = pack8h(acc[i]);
            float s = acc[i][0] * s0.x + acc[i][1] * s0.y + acc[i][2] * s0.z + acc[i][3] * s0.w
                    + acc[i][4] * s1.x + acc[i][5] * s1.y + acc[i][6] * s1.z + acc[i][7] * s1.w;
            float d = acc[i][0] * d0.x + acc[i][1] * d0.y + acc[i][2] * d0.z + acc[i][3] * d0.w
                    + acc[i][4] * d1.x + acc[i][5] * d1.y + acc[i][6] * d1.z + acc[i][7] * d1.w;
            g_als1[node * 8 + h] = s * L2E;
            g_ald1[node * 8 + h] = d * L2E;
        }
    }
}

// ---------------- GEMM 2 + fused al2 (logits pre-scaled by log2 e) ----------------
__global__ __launch_bounds__(128) void gemm2_kernel(const float* __restrict__ W,
                                                    const float* __restrict__ a_src,
                                                    const float* __restrict__ a_dst) {
    __shared__ float Xs[32 * 132];
    __shared__ float Ws[32 * 64];
    const int n0 = blockIdx.x * 128;
    const int t  = threadIdx.x;
    float acc[8][8];
#pragma unroll
    for (int i = 0; i < 8; i++)
#pragma unroll
        for (int j = 0; j < 8; j++) acc[i][j] = 0.f;
    const int ni = (t & 15) * 8;
    const int ji = (t >> 4) * 8;

    for (int kc = 0; kc < 64; kc += 32) {
        __syncthreads();
#pragma unroll
        for (int i = 0; i < 8; i++) {
            int idx = t + i * 128;
            int k4  = idx & 7;
            int n   = idx >> 3;
            int node = n0 + n;
            float4 v = make_float4(0.f, 0.f, 0.f, 0.f);
            if (node < NN) v = __ldg((const float4*)g_agg1 + node * 16 + (kc >> 2) + k4);
            Xs[(k4 * 4 + 0) * 132 + n] = v.x;
            Xs[(k4 * 4 + 1) * 132 + n] = v.y;
            Xs[(k4 * 4 + 2) * 132 + n] = v.z;
            Xs[(k4 * 4 + 3) * 132 + n] = v.w;
        }
#pragma unroll
        for (int i = 0; i < 4; i++) {
            int idx = t + i * 128;
            ((float4*)Ws)[idx] = __ldg((const float4*)W + kc * 16 + idx);
        }
        __syncthreads();
#pragma unroll
        for (int k = 0; k < 32; k++) {
            const float4 a0 = *(const float4*)(Xs + k * 132 + ni);
            const float4 a1 = *(const float4*)(Xs + k * 132 + ni + 4);
            const float4 b0 = *(const float4*)(Ws + k * 64 + ji);
            const float4 b1 = *(const float4*)(Ws + k * 64 + ji + 4);
            float av[8] = {a0.x, a0.y, a0.z, a0.w, a1.x, a1.y, a1.z, a1.w};
            float bv[8] = {b0.x, b0.y, b0.z, b0.w, b1.x, b1.y, b1.z, b1.w};
#pragma unroll
            for (int i = 0; i < 8; i++)
#pragma unroll
                for (int j = 0; j < 8; j++) acc[i][j] = fmaf(av[i], bv[j], acc[i][j]);
        }
    }
    const float4 s0 = __ldg((const float4*)a_src + (ji >> 2));
    const float4 s1 = __ldg((const float4*)a_src + (ji >> 2) + 1);
    const float4 d0 = __ldg((const float4*)a_dst + (ji >> 2));
    const float4 d1 = __ldg((const float4*)a_dst + (ji >> 2) + 1);
    float sp[8], dp[8];
#pragma unroll
    for (int i = 0; i < 8; i++) {
        int node = n0 + ni + i;
        if (node < NN)
            *(uint4*)(g_h2h + node * 32 + (ji >> 1)) = pack8h(acc[i]);
        sp[i] = acc[i][0] * s0.x + acc[i][1] * s0.y + acc[i][2] * s0.z + acc[i][3] * s0.w
              + acc[i][4] * s1.x + acc[i][5] * s1.y + acc[i][6] * s1.z + acc[i][7] * s1.w;
        dp[i] = acc[i][0] * d0.x + acc[i][1] * d0.y + acc[i][2] * d0.z + acc[i][3] * d0.w
              + acc[i][4] * d1.x + acc[i][5] * d1.y + acc[i][6] * d1.z + acc[i][7] * d1.w;
    }
    __syncthreads();
    float* redS = Xs;          // [8][128]
    float* redD = Xs + 1024;   // [8][128]
    const int g = t >> 4;
#pragma unroll
    for (int i = 0; i < 8; i++) {
        redS[g * 128 + ni + i] = sp[i];
        redD[g * 128 + ni + i] = dp[i];
    }
    __syncthreads();
    int node = n0 + t;
    if (node < NN) {
        float s = 0.f, d = 0.f;
#pragma unroll
        for (int gg = 0; gg < 8; gg++) {
            s += redS[gg * 128 + t];
            d += redD[gg * 128 + t];
        }
        g_als2[node] = s * L2E;
        g_ald2[node] = d * L2E;
    }
}

// ---------------- fused den+agg layer 1: QUARTER-WARP per dst, 8 ch/lane = 1 head ----------------
__global__ __launch_bounds__(256) void agg1_kernel(const float* __restrict__ b1) {
    const int gw = (blockIdx.x * 256 + threadIdx.x) >> 5;  // global warp id
    const int l  = threadIdx.x & 31;
    const int q  = l >> 3;                // quarter 0..3
    const int c  = l & 7;                 // head / channel-octet of this lane
    const int d  = gw * 4 + q;            // NN % 4 == 0 -> always valid

    const float ald = g_ald1[d * 8 + c];
    // self loop
    float t0 = g_als1[d * 8 + c] + ald;
    float w  = exp2f(fmaxf(t0, 0.2f * t0));
    float acc[8];
    float den = w;
    {
        uint4 r = *(const uint4*)(g_h1h + d * 32 + c * 4);
        float2 u0 = __half22float2(*(__half2*)&r.x);
        float2 u1 = __half22float2(*(__half2*)&r.y);
        float2 u2 = __half22float2(*(__half2*)&r.z);
        float2 u3 = __half22float2(*(__half2*)&r.w);
        acc[0] = w * u0.x; acc[1] = w * u0.y; acc[2] = w * u1.x; acc[3] = w * u1.y;
        acc[4] = w * u2.x; acc[5] = w * u2.y; acc[6] = w * u3.x; acc[7] = w * u3.y;
    }
    const int deg = min(g_cnt[d], MAXDEG);
    int m = deg;
    m = max(m, __shfl_xor_sync(0xffffffffu, m, 8));
    m = max(m, __shfl_xor_sync(0xffffffffu, m, 16));
    const int* __restrict__ ell = g_ell + d * MAXDEG;

    for (int e0 = 0; e0 < m; e0 += 4) {
        int4 si = __ldg((const int4*)(ell + e0));
#pragma unroll
        for (int k = 0; k < 4; k++) {
            int s = (k == 0) ? si.x : (k == 1) ? si.y : (k == 2) ? si.z : si.w;
            s = (e0 + k < deg) ? s : NN;            // sentinel: ew=0, features=0
            float as = __ldg(g_als1 + s * 8 + c);
            float tt = as + ald;
            float ew = exp2f(fmaxf(tt, 0.2f * tt));
            uint4 r = __ldg((const uint4*)(g_h1h + s * 32 + c * 4));
            float2 u0 = __half22float2(*(__half2*)&r.x);
            float2 u1 = __half22float2(*(__half2*)&r.y);
            float2 u2 = __half22float2(*(__half2*)&r.z);
            float2 u3 = __half22float2(*(__half2*)&r.w);
            acc[0] = fmaf(ew, u0.x, acc[0]); acc[1] = fmaf(ew, u0.y, acc[1]);
            acc[2] = fmaf(ew, u1.x, acc[2]); acc[3] = fmaf(ew, u1.y, acc[3]);
            acc[4] = fmaf(ew, u2.x, acc[4]); acc[5] = fmaf(ew, u2.y, acc[5]);
            acc[6] = fmaf(ew, u3.x, acc[6]); acc[7] = fmaf(ew, u3.y, acc[7]);
            den += ew;
        }
    }
    float inv = 1.f / den;
    float4 bb0 = __ldg((const float4*)b1 + c * 2);
    float4 bb1 = __ldg((const float4*)b1 + c * 2 + 1);
    float4 r0, r1;
    r0.x = eluf(fmaf(acc[0], inv, bb0.x));
    r0.y = eluf(fmaf(acc[1], inv, bb0.y));
    r0.z = eluf(fmaf(acc[2], inv, bb0.z));
    r0.w = eluf(fmaf(acc[3], inv, bb0.w));
    r1.x = eluf(fmaf(acc[4], inv, bb1.x));
    r1.y = eluf(fmaf(acc[5], inv, bb1.y));
    r1.z = eluf(fmaf(acc[6], inv, bb1.z));
    r1.w = eluf(fmaf(acc[7], inv, bb1.w));
    *(float4*)(g_agg1 + d * 64 + c * 8)     = r0;
    *(float4*)(g_agg1 + d * 64 + c * 8 + 4) = r1;
}

// ---------------- fused den+agg layer 2: QUARTER-WARP per dst, 8 ch/lane ----------------
__global__ __launch_bounds__(256) void agg2_kernel(const float* __restrict__ b2,
                                                   float* __restrict__ out) {
    const int gw = (blockIdx.x * 256 + threadIdx.x) >> 5;
    const int l  = threadIdx.x & 31;
    const int q  = l >> 3;
    const int c  = l & 7;
    const int d  = gw * 4 + q;

    const float ald = g_ald2[d];
    float t0 = g_als2[d] + ald;
    float w  = exp2f(fmaxf(t0, 0.2f * t0));
    float acc[8];
    float den = w;
    {
        uint4 r = *(const uint4*)(g_h2h + d * 32 + c * 4);
        float2 u0 = __half22float2(*(__half2*)&r.x);
        float2 u1 = __half22float2(*(__half2*)&r.y);
        float2 u2 = __half22float2(*(__half2*)&r.z);
        float2 u3 = __half22float2(*(__half2*)&r.w);
        acc[0] = w * u0.x; acc[1] = w * u0.y; acc[2] = w * u1.x; acc[3] = w * u1.y;
        acc[4] = w * u2.x; acc[5] = w * u2.y; acc[6] = w * u3.x; acc[7] = w * u3.y;
    }
    const int deg = min(g_cnt[d], MAXDEG);
    int m = deg;
    m = max(m, __shfl_xor_sync(0xffffffffu, m, 8));
    m = max(m, __shfl_xor_sync(0xffffffffu, m, 16));
    const int* __restrict__ ell = g_ell + d * MAXDEG;

    for (int e0 = 0; e0 < m; e0 += 4) {
        int4 si = __ldg((const int4*)(ell + e0));
#pragma unroll
        for (int k = 0; k < 4; k++) {
            int s = (k == 0) ? si.x : (k == 1) ? si.y : (k == 2) ? si.z : si.w;
            s = (e0 + k < deg) ? s : NN;
            float as = __ldg(g_als2 + s);            // broadcast within quarter
            float tt = as + ald;
            float ew = exp2f(fmaxf(tt, 0.2f * tt));
            uint4 r = __ldg((const uint4*)(g_h2h + s * 32 + c * 4));
            float2 u0 = __half22float2(*(__half2*)&r.x);
            float2 u1 = __half22float2(*(__half2*)&r.y);
            float2 u2 = __half22float2(*(__half2*)&r.z);
            float2 u3 = __half22float2(*(__half2*)&r.w);
            acc[0] = fmaf(ew, u0.x, acc[0]); acc[1] = fmaf(ew, u0.y, acc[1]);
            acc[2] = fmaf(ew, u1.x, acc[2]); acc[3] = fmaf(ew, u1.y, acc[3]);
            acc[4] = fmaf(ew, u2.x, acc[4]); acc[5] = fmaf(ew, u2.y, acc[5]);
            acc[6] = fmaf(ew, u3.x, acc[6]); acc[7] = fmaf(ew, u3.y, acc[7]);
            den += ew;
        }
    }
    float inv = 1.f / den;
    float4 bb0 = __ldg((const float4*)b2 + c * 2);
    float4 bb1 = __ldg((const float4*)b2 + c * 2 + 1);
    float4 r0, r1;
    r0.x = fmaf(acc[0], inv, bb0.x);
    r0.y = fmaf(acc[1], inv, bb0.y);
    r0.z = fmaf(acc[2], inv, bb0.z);
    r0.w = fmaf(acc[3], inv, bb0.w);
    r1.x = fmaf(acc[4], inv, bb1.x);
    r1.y = fmaf(acc[5], inv, bb1.y);
    r1.z = fmaf(acc[6], inv, bb1.z);
    r1.w = fmaf(acc[7], inv, bb1.w);
    *(float4*)(out + d * 64 + c * 8)     = r0;
    *(float4*)(out + d * 64 + c * 8 + 4) = r1;
}

// ---------------- launch ----------------
extern "C" void kernel_launch(void* const* d_in, const int* in_sizes, int n_in,
                              void* d_out, int out_size) {
    const float* x   = (const float*)d_in[0];
    const int*   ei  = (const int*)d_in[1];
    const float* W1  = (const float*)d_in[2];
    const float* as1 = (const float*)d_in[3];
    const float* ad1 = (const float*)d_in[4];
    const float* b1  = (const float*)d_in[5];
    const float* W2  = (const float*)d_in[6];
    const float* as2 = (const float*)d_in[7];
    const float* ad2 = (const float*)d_in[8];
    const float* b2  = (const float*)d_in[9];
    float* out = (float*)d_out;

    const int GB = (NN + 127) / 128;
    const int AGGB = NN / 32;           // 4 dsts/warp (quarter-warp each), 8 warps/block

    zero_cnt_kernel<<<(NN + 255) / 256, 256>>>();
    build_ell_kernel<<<(EE + 255) / 256, 256>>>(ei);
    gemm1_kernel<<<GB, 128>>>(x, W1, as1, ad1);
    agg1_kernel<<<AGGB, 256>>>(b1);
    gemm2_kernel<<<GB, 128>>>(W2, as2, ad2);
    agg2_kernel<<<AGGB, 256>>>(b2, out);
}

// round 9
// speedup vs baseline: 1.7091x; 1.1884x over previous
#include <cuda_runtime.h>
#include <cuda_fp16.h>
#include <mma.h>
using namespace nvcuda;

#define NN 100000
#define EE 1600000
#define MAXDEG 64
#define L2E 1.44269504f

// ---------------- scratch (device globals; +1 sentinel row at index NN) ----------------
__device__ __half2 g_h1h[(NN + 1) * 32];  // layer-1 features, fp16 pairs
__device__ __half2 g_h2h[(NN + 1) * 32];  // layer-2 features, fp16 pairs
__device__ float g_als1[(NN + 1) * 8];    // src logits * log2(e); sentinel = -1e30
__device__ float g_ald1[NN * 8];          // dst logits * log2(e)
__device__ float g_agg1[NN * 64];         // layer-1 output: elu(agg + b1), fp32
__device__ float g_als2[NN + 1];
__device__ float g_ald2[NN];
__device__ int   g_cnt[NN];               // per-dst in-degree counters
__device__ int   g_ell[NN * MAXDEG];      // padded per-dst src lists

__device__ __forceinline__ float eluf(float x)  { return x > 0.f ? x : expm1f(x); }

// ---------------- init: counters + sentinel rows ----------------
__global__ void zero_cnt_kernel() {
    int n = blockIdx.x * 256 + threadIdx.x;
    if (n < NN) g_cnt[n] = 0;
    if (n < 32) {
        g_h1h[NN * 32 + n] = __floats2half2_rn(0.f, 0.f);
        g_h2h[NN * 32 + n] = __floats2half2_rn(0.f, 0.f);
    }
    if (n < 8) g_als1[NN * 8 + n] = -1e30f;
    if (n == 0) g_als2[NN] = -1e30f;
}

__global__ void build_ell_kernel(const int* __restrict__ ei) {
    int e = blockIdx.x * 256 + threadIdx.x;
    if (e >= EE) return;
    int s = __ldg(ei + e), d = __ldg(ei + EE + e);
    int p = atomicAdd(g_cnt + d, 1);
    if (p < MAXDEG) g_ell[d * MAXDEG + p] = s;
}

// ---------------- GEMM 1 (wmma fp16) + fused al1 ----------------
// C[128 rows x 64] = x[128 x 128] @ W1[128 x 64]; 4 warps, each 32 rows.
#define LDA 72
#define LDB 72
#define LDC 68
__global__ __launch_bounds__(128) void gemm1_tc(const float* __restrict__ x,
                                                const float* __restrict__ W,
                                                const float* __restrict__ a_src,
                                                const float* __restrict__ a_dst) {
    __shared__ __align__(16) char smem[36864];
    __half* Ah = (__half*)smem;              // [128][LDA] chunk of 64 k
    __half* Bh = (__half*)(smem + 18432);    // [128][LDB] all of W1
    float*  Cs = (float*)smem;               // [128][LDC] epilogue (aliases A/B)

    const int n0 = blockIdx.x * 128;
    const int t  = threadIdx.x;
    const int w  = t >> 5;

    wmma::fragment<wmma::accumulator, 16, 16, 16, float> acc[2][4];
#pragma unroll
    for (int i = 0; i < 2; i++)
#pragma unroll
        for (int j = 0; j < 4; j++) wmma::fill_fragment(acc[i][j], 0.f);

    // load all of B = W1 [k=128][n=64] (row-major == matrix_b row_major)
#pragma unroll
    for (int i = 0; i < 16; i++) {
        int idx = t + i * 128;               // 0..2047 float4s
        int k = idx >> 4, n4 = idx & 15;
        float4 v = __ldg((const float4*)W + idx);
        __half2 p0 = __floats2half2_rn(v.x, v.y);
        __half2 p1 = __floats2half2_rn(v.z, v.w);
        *(__half2*)(Bh + k * LDB + n4 * 4)     = p0;
        *(__half2*)(Bh + k * LDB + n4 * 4 + 2) = p1;
    }

    for (int kc = 0; kc < 128; kc += 64) {
        __syncthreads();
#pragma unroll
        for (int i = 0; i < 16; i++) {
            int idx = t + i * 128;           // 0..2047 float4s
            int row = idx >> 4, k4 = idx & 15;
            int node = n0 + row;
            float4 v = make_float4(0.f, 0.f, 0.f, 0.f);
            if (node < NN) v = __ldg((const float4*)x + node * 32 + (kc >> 2) + k4);
            __half2 p0 = __floats2half2_rn(v.x, v.y);
            __half2 p1 = __floats2half2_rn(v.z, v.w);
            *(__half2*)(Ah + row * LDA + k4 * 4)     = p0;
            *(__half2*)(Ah + row * LDA + k4 * 4 + 2) = p1;
        }
        __syncthreads();
#pragma unroll
        for (int kk = 0; kk < 64; kk += 16) {
            wmma::fragment<wmma::matrix_a, 16, 16, 16, __half, wmma::row_major> a0, a1;
            wmma::load_matrix_sync(a0, Ah + (w * 32)      * LDA + kk, LDA);
            wmma::load_matrix_sync(a1, Ah + (w * 32 + 16) * LDA + kk, LDA);
#pragma unroll
            for (int j = 0; j < 4; j++) {
                wmma::fragment<wmma::matrix_b, 16, 16, 16, __half, wmma::row_major> b;
                wmma::load_matrix_sync(b, Bh + (kc + kk) * LDB + j * 16, LDB);
                wmma::mma_sync(acc[0][j], a0, b, acc[0][j]);
                wmma::mma_sync(acc[1][j], a1, b, acc[1][j]);
            }
        }
    }
    __syncthreads();   // done reading Ah/Bh; Cs aliases them
#pragma unroll
    for (int i = 0; i < 2; i++)
#pragma unroll
        for (int j = 0; j < 4; j++)
            wmma::store_matrix_sync(Cs + (w * 32 + i * 16) * LDC + j * 16,
                                    acc[i][j], LDC, wmma::mem_row_major);
    __syncthreads();

    // epilogue: thread t owns row t
    int node = n0 + t;
    if (node < NN) {
        const float4* crow = (const float4*)(Cs + t * LDC);
        float sb[8], db[8];
#pragma unroll
        for (int h = 0; h < 8; h++) {
            float4 c0 = crow[h * 2], c1 = crow[h * 2 + 1];
            float4 s0 = __ldg((const float4*)a_src + h * 2);
            float4 s1 = __ldg((const float4*)a_src + h * 2 + 1);
            float4 d0 = __ldg((const float4*)a_dst + h * 2);
            float4 d1 = __ldg((const float4*)a_dst + h * 2 + 1);
            sb[h] = (c0.x * s0.x + c0.y * s0.y + c0.z * s0.z + c0.w * s0.w
                   + c1.x * s1.x + c1.y * s1.y + c1.z * s1.z + c1.w * s1.w) * L2E;
            db[h] = (c0.x * d0.x + c0.y * d0.y + c0.z * d0.z + c0.w * d0.w
                   + c1.x * d1.x + c1.y * d1.y + c1.z * d1.z + c1.w * d1.w) * L2E;
            uint4 p;
            __half2 h0 = __floats2half2_rn(c0.x, c0.y);
            __half2 h1 = __floats2half2_rn(c0.z, c0.w);
            __half2 h2 = __floats2half2_rn(c1.x, c1.y);
            __half2 h3 = __floats2half2_rn(c1.z, c1.w);
            p.x = *(unsigned*)&h0; p.y = *(unsigned*)&h1;
            p.z = *(unsigned*)&h2; p.w = *(unsigned*)&h3;
            *(uint4*)(g_h1h + node * 32 + h * 4) = p;
        }
        *(float4*)(g_als1 + node * 8)     = make_float4(sb[0], sb[1], sb[2], sb[3]);
        *(float4*)(g_als1 + node * 8 + 4) = make_float4(sb[4], sb[5], sb[6], sb[7]);
        *(float4*)(g_ald1 + node * 8)     = make_float4(db[0], db[1], db[2], db[3]);
        *(float4*)(g_ald1 + node * 8 + 4) = make_float4(db[4], db[5], db[6], db[7]);
    }
}

// ---------------- GEMM 2 (wmma fp16) + fused al2 ----------------
// C[128 x 64] = agg1[128 x 64] @ W2[64 x 64]
__global__ __launch_bounds__(128) void gemm2_tc(const float* __restrict__ W,
                                                const float* __restrict__ a_src,
                                                const float* __restrict__ a_dst) {
    __shared__ __align__(16) char smem[36864];
    __half* Ah = (__half*)smem;              // [128][LDA], k=64
    __half* Bh = (__half*)(smem + 18432);    // [64][LDB]
    float*  Cs = (float*)smem;               // [128][LDC]

    const int n0 = blockIdx.x * 128;
    const int t  = threadIdx.x;
    const int w  = t >> 5;

    wmma::fragment<wmma::accumulator, 16, 16, 16, float> acc[2][4];
#pragma unroll
    for (int i = 0; i < 2; i++)
#pragma unroll
        for (int j = 0; j < 4; j++) wmma::fill_fragment(acc[i][j], 0.f);

    // B = W2 [64][64]
#pragma unroll
    for (int i = 0; i < 8; i++) {
        int idx = t + i * 128;               // 0..1023 float4s
        int k = idx >> 4, n4 = idx & 15;
        float4 v = __ldg((const float4*)W + idx);
        __half2 p0 = __floats2half2_rn(v.x, v.y);
        __half2 p1 = __floats2half2_rn(v.z, v.w);
        *(__half2*)(Bh + k * LDB + n4 * 4)     = p0;
        *(__half2*)(Bh + k * LDB + n4 * 4 + 2) = p1;
    }
    // A = agg1 chunk (full K=64)
#pragma unroll
    for (int i = 0; i < 16; i++) {
        int idx = t + i * 128;
        int row = idx >> 4, k4 = idx & 15;
        int node = n0 + row;
        float4 v = make_float4(0.f, 0.f, 0.f, 0.f);
        if (node < NN) v = __ldg((const float4*)g_agg1 + node * 16 + k4);
        __half2 p0 = __floats2half2_rn(v.x, v.y);
        __half2 p1 = __floats2half2_rn(v.z, v.w);
        *(__half2*)(Ah + row * LDA + k4 * 4)     = p0;
        *(__half2*)(Ah + row * LDA + k4 * 4 + 2) = p1;
    }
    __syncthreads();
#pragma unroll
    for (int kk = 0; kk < 64; kk += 16) {
        wmma::fragment<wmma::matrix_a, 16, 16, 16, __half, wmma::row_major> a0, a1;
        wmma::load_matrix_sync(a0, Ah + (w * 32)      * LDA + kk, LDA);
        wmma::load_matrix_sync(a1, Ah + (w * 32 + 16) * LDA + kk, LDA);
#pragma unroll
        for (int j = 0; j < 4; j++) {
            wmma::fragment<wmma::matrix_b, 16, 16, 16, __half, wmma::row_major> b;
            wmma::load_matrix_sync(b, Bh + kk * LDB + j * 16, LDB);
            wmma::mma_sync(acc[0][j], a0, b, acc[0][j]);
            wmma::mma_sync(acc[1][j], a1, b, acc[1][j]);
        }
    }
    __syncthreads();
#pragma unroll
    for (int i = 0; i < 2; i++)
#pragma unroll
        for (int j = 0; j < 4; j++)
            wmma::store_matrix_sync(Cs + (w * 32 + i * 16) * LDC + j * 16,
                                    acc[i][j], LDC, wmma::mem_row_major);
    __syncthreads();

    int node = n0 + t;
    if (node < NN) {
        const float4* crow = (const float4*)(Cs + t * LDC);
        float s = 0.f, d = 0.f;
#pragma unroll
        for (int i = 0; i < 16; i++) {
            float4 c = crow[i];
            float4 sa = __ldg((const float4*)a_src + i);
            float4 da = __ldg((const float4*)a_dst + i);
            s += c.x * sa.x + c.y * sa.y + c.z * sa.z + c.w * sa.w;
            d += c.x * da.x + c.y * da.y + c.z * da.z + c.w * da.w;
            uint4 p;
            __half2 h0 = __floats2half2_rn(c.x, c.y);
            __half2 h1 = __floats2half2_rn(c.z, c.w);
            p.x = *(unsigned*)&h0; p.y = *(unsigned*)&h1;
            if (i & 1) {
                // complete the 16B record with previous half-pack
            }
            // store 8B (4 halves) each iteration
            *(__half2*)(g_h2h + node * 32 + i * 2)     = h0;
            *(__half2*)(g_h2h + node * 32 + i * 2 + 1) = h1;
        }
        g_als2[node] = s * L2E;
        g_ald2[node] = d * L2E;
    }
}

// ---------------- fused den+agg layer 1: QUARTER-WARP per dst, 8 ch/lane = 1 head ----------------
__global__ __launch_bounds__(256) void agg1_kernel(const float* __restrict__ b1) {
    const int gw = (blockIdx.x * 256 + threadIdx.x) >> 5;
    const int l  = threadIdx.x & 31;
    const int q  = l >> 3;
    const int c  = l & 7;
    const int d  = gw * 4 + q;

    const float ald = g_ald1[d * 8 + c];
    float t0 = g_als1[d * 8 + c] + ald;
    float w  = exp2f(fmaxf(t0, 0.2f * t0));
    float acc[8];
    float den = w;
    {
        uint4 r = *(const uint4*)(g_h1h + d * 32 + c * 4);
        float2 u0 = __half22float2(*(__half2*)&r.x);
        float2 u1 = __half22float2(*(__half2*)&r.y);
        float2 u2 = __half22float2(*(__half2*)&r.z);
        float2 u3 = __half22float2(*(__half2*)&r.w);
        acc[0] = w * u0.x; acc[1] = w * u0.y; acc[2] = w * u1.x; acc[3] = w * u1.y;
        acc[4] = w * u2.x; acc[5] = w * u2.y; acc[6] = w * u3.x; acc[7] = w * u3.y;
    }
    const int deg = min(g_cnt[d], MAXDEG);
    int m = deg;
    m = max(m, __shfl_xor_sync(0xffffffffu, m, 8));
    m = max(m, __shfl_xor_sync(0xffffffffu, m, 16));
    const int* __restrict__ ell = g_ell + d * MAXDEG;

    for (int e0 = 0; e0 < m; e0 += 4) {
        int4 si = __ldg((const int4*)(ell + e0));
#pragma unroll
        for (int k = 0; k < 4; k++) {
            int s = (k == 0) ? si.x : (k == 1) ? si.y : (k == 2) ? si.z : si.w;
            s = (e0 + k < deg) ? s : NN;
            float as = __ldg(g_als1 + s * 8 + c);
            float tt = as + ald;
            float ew = exp2f(fmaxf(tt, 0.2f * tt));
            uint4 r = __ldg((const uint4*)(g_h1h + s * 32 + c * 4));
            float2 u0 = __half22float2(*(__half2*)&r.x);
            float2 u1 = __half22float2(*(__half2*)&r.y);
            float2 u2 = __half22float2(*(__half2*)&r.z);
            float2 u3 = __half22float2(*(__half2*)&r.w);
            acc[0] = fmaf(ew, u0.x, acc[0]); acc[1] = fmaf(ew, u0.y, acc[1]);
            acc[2] = fmaf(ew, u1.x, acc[2]); acc[3] = fmaf(ew, u1.y, acc[3]);
            acc[4] = fmaf(ew, u2.x, acc[4]); acc[5] = fmaf(ew, u2.y, acc[5]);
            acc[6] = fmaf(ew, u3.x, acc[6]); acc[7] = fmaf(ew, u3.y, acc[7]);
            den += ew;
        }
    }
    float inv = 1.f / den;
    float4 bb0 = __ldg((const float4*)b1 + c * 2);
    float4 bb1 = __ldg((const float4*)b1 + c * 2 + 1);
    float4 r0, r1;
    r0.x = eluf(fmaf(acc[0], inv, bb0.x));
    r0.y = eluf(fmaf(acc[1], inv, bb0.y));
    r0.z = eluf(fmaf(acc[2], inv, bb0.z));
    r0.w = eluf(fmaf(acc[3], inv, bb0.w));
    r1.x = eluf(fmaf(acc[4], inv, bb1.x));
    r1.y = eluf(fmaf(acc[5], inv, bb1.y));
    r1.z = eluf(fmaf(acc[6], inv, bb1.z));
    r1.w = eluf(fmaf(acc[7], inv, bb1.w));
    *(float4*)(g_agg1 + d * 64 + c * 8)     = r0;
    *(float4*)(g_agg1 + d * 64 + c * 8 + 4) = r1;
}

// ---------------- fused den+agg layer 2: QUARTER-WARP per dst, 8 ch/lane ----------------
__global__ __launch_bounds__(256) void agg2_kernel(const float* __restrict__ b2,
                                                   float* __restrict__ out) {
    const int gw = (blockIdx.x * 256 + threadIdx.x) >> 5;
    const int l  = threadIdx.x & 31;
    const int q  = l >> 3;
    const int c  = l & 7;
    const int d  = gw * 4 + q;

    const float ald = g_ald2[d];
    float t0 = g_als2[d] + ald;
    float w  = exp2f(fmaxf(t0, 0.2f * t0));
    float acc[8];
    float den = w;
    {
        uint4 r = *(const uint4*)(g_h2h + d * 32 + c * 4);
        float2 u0 = __half22float2(*(__half2*)&r.x);
        float2 u1 = __half22float2(*(__half2*)&r.y);
        float2 u2 = __half22float2(*(__half2*)&r.z);
        float2 u3 = __half22float2(*(__half2*)&r.w);
        acc[0] = w * u0.x; acc[1] = w * u0.y; acc[2] = w * u1.x; acc[3] = w * u1.y;
        acc[4] = w * u2.x; acc[5] = w * u2.y; acc[6] = w * u3.x; acc[7] = w * u3.y;
    }
    const int deg = min(g_cnt[d], MAXDEG);
    int m = deg;
    m = max(m, __shfl_xor_sync(0xffffffffu, m, 8));
    m = max(m, __shfl_xor_sync(0xffffffffu, m, 16));
    const int* __restrict__ ell = g_ell + d * MAXDEG;

    for (int e0 = 0; e0 < m; e0 += 4) {
        int4 si = __ldg((const int4*)(ell + e0));
#pragma unroll
        for (int k = 0; k < 4; k++) {
            int s = (k == 0) ? si.x : (k == 1) ? si.y : (k == 2) ? si.z : si.w;
            s = (e0 + k < deg) ? s : NN;
            float as = __ldg(g_als2 + s);
            float tt = as + ald;
            float ew = exp2f(fmaxf(tt, 0.2f * tt));
            uint4 r = __ldg((const uint4*)(g_h2h + s * 32 + c * 4));
            float2 u0 = __half22float2(*(__half2*)&r.x);
            float2 u1 = __half22float2(*(__half2*)&r.y);
            float2 u2 = __half22float2(*(__half2*)&r.z);
            float2 u3 = __half22float2(*(__half2*)&r.w);
            acc[0] = fmaf(ew, u0.x, acc[0]); acc[1] = fmaf(ew, u0.y, acc[1]);
            acc[2] = fmaf(ew, u1.x, acc[2]); acc[3] = fmaf(ew, u1.y, acc[3]);
            acc[4] = fmaf(ew, u2.x, acc[4]); acc[5] = fmaf(ew, u2.y, acc[5]);
            acc[6] = fmaf(ew, u3.x, acc[6]); acc[7] = fmaf(ew, u3.y, acc[7]);
            den += ew;
        }
    }
    float inv = 1.f / den;
    float4 bb0 = __ldg((const float4*)b2 + c * 2);
    float4 bb1 = __ldg((const float4*)b2 + c * 2 + 1);
    float4 r0, r1;
    r0.x = fmaf(acc[0], inv, bb0.x);
    r0.y = fmaf(acc[1], inv, bb0.y);
    r0.z = fmaf(acc[2], inv, bb0.z);
    r0.w = fmaf(acc[3], inv, bb0.w);
    r1.x = fmaf(acc[4], inv, bb1.x);
    r1.y = fmaf(acc[5], inv, bb1.y);
    r1.z = fmaf(acc[6], inv, bb1.z);
    r1.w = fmaf(acc[7], inv, bb1.w);
    *(float4*)(out + d * 64 + c * 8)     = r0;
    *(float4*)(out + d * 64 + c * 8 + 4) = r1;
}

// ---------------- launch ----------------
extern "C" void kernel_launch(void* const* d_in, const int* in_sizes, int n_in,
                              void* d_out, int out_size) {
    const float* x   = (const float*)d_in[0];
    const int*   ei  = (const int*)d_in[1];
    const float* W1  = (const float*)d_in[2];
    const float* as1 = (const float*)d_in[3];
    const float* ad1 = (const float*)d_in[4];
    const float* b1  = (const float*)d_in[5];
    const float* W2  = (const float*)d_in[6];
    const float* as2 = (const float*)d_in[7];
    const float* ad2 = (const float*)d_in[8];
    const float* b2  = (const float*)d_in[9];
    float* out = (float*)d_out;

    const int GB = (NN + 127) / 128;
    const int AGGB = NN / 32;

    zero_cnt_kernel<<<(NN + 255) / 256, 256>>>();
    build_ell_kernel<<<(EE + 255) / 256, 256>>>(ei);
    gemm1_tc<<<GB, 128>>>(x, W1, as1, ad1);
    agg1_kernel<<<AGGB, 256>>>(b1);
    gemm2_tc<<<GB, 128>>>(W2, as2, ad2);
    agg2_kernel<<<AGGB, 256>>>(b2, out);
}

// round 15
// speedup vs baseline: 1.7975x; 1.0517x over previous
#include <cuda_runtime.h>
#include <cuda_fp16.h>
#include <mma.h>
using namespace nvcuda;

#define NN 100000
#define EE 1600000
#define MAXDEG 64
#define L2E 1.44269504f

// ---------------- scratch (device globals; +1 sentinel row at index NN) ----------------
__device__ __half2 g_h1h[(NN + 1) * 32];  // layer-1 features, fp16 pairs
__device__ __half2 g_h2h[(NN + 1) * 32];  // layer-2 features, fp16 pairs
__device__ __half2 g_agg1h[NN * 32];      // layer-1 output: elu(agg+b1), fp16 (gemm2 A)
__device__ float g_als1[(NN + 1) * 8];    // src logits * log2(e); sentinel = -1e30
__device__ float g_ald1[NN * 8];          // dst logits * log2(e)
__device__ float g_als2[NN + 1];
__device__ float g_ald2[NN];
__device__ int   g_cnt[NN];               // per-dst in-degree counters
__device__ int   g_ell[NN * MAXDEG];      // padded per-dst src lists (pre-filled with NN)

__device__ __forceinline__ float eluf(float x)  { return x > 0.f ? x : expm1f(x); }

// ---- packed f32x2 helpers (FFMA2 path, PTX-only) ----
__device__ __forceinline__ unsigned long long packf2(float lo, float hi) {
    unsigned long long r;
    asm("mov.b64 %0, {%1, %2};" : "=l"(r) : "f"(lo), "f"(hi));
    return r;
}
__device__ __forceinline__ float2 unpackf2(unsigned long long v) {
    float2 r;
    asm("mov.b64 {%0, %1}, %2;" : "=f"(r.x), "=f"(r.y) : "l"(v));
    return r;
}
__device__ __forceinline__ unsigned long long h2f2(unsigned h2) {
    unsigned long long r;
    asm("{.reg .b16 l, h; .reg .f32 fl, fh;\n\t"
        "mov.b32 {l, h}, %1;\n\t"
        "cvt.f32.f16 fl, l;\n\t"
        "cvt.f32.f16 fh, h;\n\t"
        "mov.b64 %0, {fl, fh};}" : "=l"(r) : "r"(h2));
    return r;
}
__device__ __forceinline__ unsigned long long mulf2(unsigned long long a, unsigned long long b) {
    unsigned long long r;
    asm("mul.rn.f32x2 %0, %1, %2;" : "=l"(r) : "l"(a), "l"(b));
    return r;
}
__device__ __forceinline__ void ffma2(unsigned long long& acc, unsigned long long a,
                                      unsigned long long b) {
    asm("fma.rn.f32x2 %0, %1, %2, %0;" : "+l"(acc) : "l"(a), "l"(b));
}

// ---------------- init: counters + sentinel rows ----------------
__global__ void zero_cnt_kernel() {
    int n = blockIdx.x * 256 + threadIdx.x;
    if (n < NN) g_cnt[n] = 0;
    if (n < 32) {
        g_h1h[NN * 32 + n] = __floats2half2_rn(0.f, 0.f);
        g_h2h[NN * 32 + n] = __floats2half2_rn(0.f, 0.f);
    }
    if (n < 8) g_als1[NN * 8 + n] = -1e30f;
    if (n == 0) g_als2[NN] = -1e30f;
}

// pre-fill ELL with sentinel NN (branch-free agg inner loops)
__global__ void pad_ell_kernel() {
    int i = blockIdx.x * 256 + threadIdx.x;
    if (i < NN * (MAXDEG / 4)) ((int4*)g_ell)[i] = make_int4(NN, NN, NN, NN);
}

__global__ void build_ell_kernel(const int* __restrict__ ei) {
    int e = blockIdx.x * 256 + threadIdx.x;
    if (e >= EE) return;
    int s = __ldg(ei + e), d = __ldg(ei + EE + e);
    int p = atomicAdd(g_cnt + d, 1);
    if (p < MAXDEG) g_ell[d * MAXDEG + p] = s;
}

// ---------------- GEMM 1 (wmma fp16) + fused al1 ----------------
#define LDA 72
#define LDB 72
#define LDC 68
__global__ __launch_bounds__(128) void gemm1_tc(const float* __restrict__ x,
                                                const float* __restrict__ W,
                                                const float* __restrict__ a_src,
                                                const float* __restrict__ a_dst) {
    __shared__ __align__(16) char smem[36864];
    __half* Ah = (__half*)smem;              // [128][LDA] chunk of 64 k
    __half* Bh = (__half*)(smem + 18432);    // [128][LDB] all of W1
    float*  Cs = (float*)smem;               // [128][LDC] epilogue (aliases A/B)

    const int n0 = blockIdx.x * 128;
    const int t  = threadIdx.x;
    const int w  = t >> 5;

    wmma::fragment<wmma::accumulator, 16, 16, 16, float> acc[2][4];
#pragma unroll
    for (int i = 0; i < 2; i++)
#pragma unroll
        for (int j = 0; j < 4; j++) wmma::fill_fragment(acc[i][j], 0.f);

#pragma unroll
    for (int i = 0; i < 16; i++) {
        int idx = t + i * 128;
        int k = idx >> 4, n4 = idx & 15;
        float4 v = __ldg((const float4*)W + idx);
        __half2 p0 = __floats2half2_rn(v.x, v.y);
        __half2 p1 = __floats2half2_rn(v.z, v.w);
        *(__half2*)(Bh + k * LDB + n4 * 4)     = p0;
        *(__half2*)(Bh + k * LDB + n4 * 4 + 2) = p1;
    }

    for (int kc = 0; kc < 128; kc += 64) {
        __syncthreads();
#pragma unroll
        for (int i = 0; i < 16; i++) {
            int idx = t + i * 128;
            int row = idx >> 4, k4 = idx & 15;
            int node = n0 + row;
            float4 v = make_float4(0.f, 0.f, 0.f, 0.f);
            if (node < NN) v = __ldg((const float4*)x + node * 32 + (kc >> 2) + k4);
            __half2 p0 = __floats2half2_rn(v.x, v.y);
            __half2 p1 = __floats2half2_rn(v.z, v.w);
            *(__half2*)(Ah + row * LDA + k4 * 4)     = p0;
            *(__half2*)(Ah + row * LDA + k4 * 4 + 2) = p1;
        }
        __syncthreads();
#pragma unroll
        for (int kk = 0; kk < 64; kk += 16) {
            wmma::fragment<wmma::matrix_a, 16, 16, 16, __half, wmma::row_major> a0, a1;
            wmma::load_matrix_sync(a0, Ah + (w * 32)      * LDA + kk, LDA);
            wmma::load_matrix_sync(a1, Ah + (w * 32 + 16) * LDA + kk, LDA);
#pragma unroll
            for (int j = 0; j < 4; j++) {
                wmma::fragment<wmma::matrix_b, 16, 16, 16, __half, wmma::row_major> b;
                wmma::load_matrix_sync(b, Bh + (kc + kk) * LDB + j * 16, LDB);
                wmma::mma_sync(acc[0][j], a0, b, acc[0][j]);
                wmma::mma_sync(acc[1][j], a1, b, acc[1][j]);
            }
        }
    }
    __syncthreads();
#pragma unroll
    for (int i = 0; i < 2; i++)
#pragma unroll
        for (int j = 0; j < 4; j++)
            wmma::store_matrix_sync(Cs + (w * 32 + i * 16) * LDC + j * 16,
                                    acc[i][j], LDC, wmma::mem_row_major);
    __syncthreads();

    int node = n0 + t;
    if (node < NN) {
        const float4* crow = (const float4*)(Cs + t * LDC);
        float sb[8], db[8];
#pragma unroll
        for (int h = 0; h < 8; h++) {
            float4 c0 = crow[h * 2], c1 = crow[h * 2 + 1];
            float4 s0 = __ldg((const float4*)a_src + h * 2);
            float4 s1 = __ldg((const float4*)a_src + h * 2 + 1);
            float4 d0 = __ldg((const float4*)a_dst + h * 2);
            float4 d1 = __ldg((const float4*)a_dst + h * 2 + 1);
            sb[h] = (c0.x * s0.x + c0.y * s0.y + c0.z * s0.z + c0.w * s0.w
                   + c1.x * s1.x + c1.y * s1.y + c1.z * s1.z + c1.w * s1.w) * L2E;
            db[h] = (c0.x * d0.x + c0.y * d0.y + c0.z * d0.z + c0.w * d0.w
                   + c1.x * d1.x + c1.y * d1.y + c1.z * d1.z + c1.w * d1.w) * L2E;
            uint4 p;
            __half2 h0 = __floats2half2_rn(c0.x, c0.y);
            __half2 h1 = __floats2half2_rn(c0.z, c0.w);
            __half2 h2 = __floats2half2_rn(c1.x, c1.y);
            __half2 h3 = __floats2half2_rn(c1.z, c1.w);
            p.x = *(unsigned*)&h0; p.y = *(unsigned*)&h1;
            p.z = *(unsigned*)&h2; p.w = *(unsigned*)&h3;
            *(uint4*)(g_h1h + node * 32 + h * 4) = p;
        }
        *(float4*)(g_als1 + node * 8)     = make_float4(sb[0], sb[1], sb[2], sb[3]);
        *(float4*)(g_als1 + node * 8 + 4) = make_float4(sb[4], sb[5], sb[6], sb[7]);
        *(float4*)(g_ald1 + node * 8)     = make_float4(db[0], db[1], db[2], db[3]);
        *(float4*)(g_ald1 + node * 8 + 4) = make_float4(db[4], db[5], db[6], db[7]);
    }
}

// ---------------- GEMM 2 (wmma fp16, A already fp16) + fused al2 ----------------
__global__ __launch_bounds__(128) void gemm2_tc(const float* __restrict__ W,
                                                const float* __restrict__ a_src,
                                                const float* __restrict__ a_dst) {
    __shared__ __align__(16) char smem[36864];
    __half* Ah = (__half*)smem;              // [128][LDA], k=64
    __half* Bh = (__half*)(smem + 18432);    // [64][LDB]
    float*  Cs = (float*)smem;               // [128][LDC]

    const int n0 = blockIdx.x * 128;
    const int t  = threadIdx.x;
    const int w  = t >> 5;

    wmma::fragment<wmma::accumulator, 16, 16, 16, float> acc[2][4];
#pragma unroll
    for (int i = 0; i < 2; i++)
#pragma unroll
        for (int j = 0; j < 4; j++) wmma::fill_fragment(acc[i][j], 0.f);

    // B = W2 [64][64] fp32 -> fp16
#pragma unroll
    for (int i = 0; i < 8; i++) {
        int idx = t + i * 128;
        int k = idx >> 4, n4 = idx & 15;
        float4 v = __ldg((const float4*)W + idx);
        __half2 p0 = __floats2half2_rn(v.x, v.y);
        __half2 p1 = __floats2half2_rn(v.z, v.w);
        *(__half2*)(Bh + k * LDB + n4 * 4)     = p0;
        *(__half2*)(Bh + k * LDB + n4 * 4 + 2) = p1;
    }
    // A = agg1h rows (fp16 already: raw 16B copies)
#pragma unroll
    for (int i = 0; i < 8; i++) {
        int idx = t + i * 128;               // 0..1023 uint4s
        int row = idx >> 3, q8 = idx & 7;    // 8 uint4 (=64 halves) per row
        int node = n0 + row;
        uint4 v = make_uint4(0u, 0u, 0u, 0u);
        if (node < NN) v = __ldg((const uint4*)(g_agg1h + node * 32) + q8);
        *(uint4*)(Ah + row * LDA + q8 * 8) = v;
    }
    __syncthreads();
#pragma unroll
    for (int kk = 0; kk < 64; kk += 16) {
        wmma::fragment<wmma::matrix_a, 16, 16, 16, __half, wmma::row_major> a0, a1;
        wmma::load_matrix_sync(a0, Ah + (w * 32)      * LDA + kk, LDA);
        wmma::load_matrix_sync(a1, Ah + (w * 32 + 16) * LDA + kk, LDA);
#pragma unroll
        for (int j = 0; j < 4; j++) {
            wmma::fragment<wmma::matrix_b, 16, 16, 16, __half, wmma::row_major> b;
            wmma::load_matrix_sync(b, Bh + kk * LDB + j * 16, LDB);
            wmma::mma_sync(acc[0][j], a0, b, acc[0][j]);
            wmma::mma_sync(acc[1][j], a1, b, acc[1][j]);
        }
    }
    __syncthreads();
#pragma unroll
    for (int i = 0; i < 2; i++)
#pragma unroll
        for (int j = 0; j < 4; j++)
            wmma::store_matrix_sync(Cs + (w * 32 + i * 16) * LDC + j * 16,
                                    acc[i][j], LDC, wmma::mem_row_major);
    __syncthreads();

    int node = n0 + t;
    if (node < NN) {
        const float4* crow = (const float4*)(Cs + t * LDC);
        float s = 0.f, d = 0.f;
#pragma unroll
        for (int i = 0; i < 16; i++) {
            float4 c = crow[i];
            float4 sa = __ldg((const float4*)a_src + i);
            float4 da = __ldg((const float4*)a_dst + i);
            s += c.x * sa.x + c.y * sa.y + c.z * sa.z + c.w * sa.w;
            d += c.x * da.x + c.y * da.y + c.z * da.z + c.w * da.w;
            __half2 h0 = __floats2half2_rn(c.x, c.y);
            __half2 h1 = __floats2half2_rn(c.z, c.w);
            *(__half2*)(g_h2h + node * 32 + i * 2)     = h0;
            *(__half2*)(g_h2h + node * 32 + i * 2 + 1) = h1;
        }
        g_als2[node] = s * L2E;
        g_ald2[node] = d * L2E;
    }
}

// ---------------- fused den+agg layer 1: quarter-warp per dst, packed f32x2 accumulate ----------------
__global__ __launch_bounds__(256) void agg1_kernel(const float* __restrict__ b1) {
    const int gw = (blockIdx.x * 256 + threadIdx.x) >> 5;
    const int l  = threadIdx.x & 31;
    const int c  = l & 7;
    const int d  = gw * 4 + (l >> 3);

    const float ald = g_ald1[d * 8 + c];
    float t0 = g_als1[d * 8 + c] + ald;
    float w  = exp2f(fmaxf(t0, 0.2f * t0));
    unsigned long long EWs = packf2(w, w);
    uint4 rs = *(const uint4*)(g_h1h + d * 32 + c * 4);
    unsigned long long a0 = mulf2(h2f2(rs.x), EWs);
    unsigned long long a1 = mulf2(h2f2(rs.y), EWs);
    unsigned long long a2 = mulf2(h2f2(rs.z), EWs);
    unsigned long long a3 = mulf2(h2f2(rs.w), EWs);
    float den = w;

    const int deg = min(g_cnt[d], MAXDEG);
    int m = deg;
    m = max(m, __shfl_xor_sync(0xffffffffu, m, 8));
    m = max(m, __shfl_xor_sync(0xffffffffu, m, 16));
    const int* __restrict__ ell = g_ell + d * MAXDEG;

    for (int e0 = 0; e0 < m; e0 += 4) {
        int4 si = __ldg((const int4*)(ell + e0));
#pragma unroll
        for (int k = 0; k < 4; k++) {
            int s = (k == 0) ? si.x : (k == 1) ? si.y : (k == 2) ? si.z : si.w;
            float as = __ldg(g_als1 + s * 8 + c);
            float tt = as + ald;
            float ew = exp2f(fmaxf(tt, 0.2f * tt));
            unsigned long long EW = packf2(ew, ew);
            uint4 r = __ldg((const uint4*)(g_h1h + s * 32 + c * 4));
            ffma2(a0, h2f2(r.x), EW);
            ffma2(a1, h2f2(r.y), EW);
            ffma2(a2, h2f2(r.z), EW);
            ffma2(a3, h2f2(r.w), EW);
            den += ew;
        }
    }
    float inv = 1.f / den;
    float2 p0 = unpackf2(a0), p1 = unpackf2(a1), p2 = unpackf2(a2), p3 = unpackf2(a3);
    float4 bb0 = __ldg((const float4*)b1 + c * 2);
    float4 bb1 = __ldg((const float4*)b1 + c * 2 + 1);
    __half2 o0 = __floats2half2_rn(eluf(fmaf(p0.x, inv, bb0.x)), eluf(fmaf(p0.y, inv, bb0.y)));
    __half2 o1 = __floats2half2_rn(eluf(fmaf(p1.x, inv, bb0.z)), eluf(fmaf(p1.y, inv, bb0.w)));
    __half2 o2 = __floats2half2_rn(eluf(fmaf(p2.x, inv, bb1.x)), eluf(fmaf(p2.y, inv, bb1.y)));
    __half2 o3 = __floats2half2_rn(eluf(fmaf(p3.x, inv, bb1.z)), eluf(fmaf(p3.y, inv, bb1.w)));
    uint4 pk;
    pk.x = *(unsigned*)&o0; pk.y = *(unsigned*)&o1;
    pk.z = *(unsigned*)&o2; pk.w = *(unsigned*)&o3;
    *(uint4*)(g_agg1h + d * 32 + c * 4) = pk;
}

// ---------------- fused den+agg layer 2: quarter-warp per dst, packed f32x2 accumulate ----------------
__global__ __launch_bounds__(256) void agg2_kernel(const float* __restrict__ b2,
                                                   float* __restrict__ out) {
    const int gw = (blockIdx.x * 256 + threadIdx.x) >> 5;
    const int l  = threadIdx.x & 31;
    const int c  = l & 7;
    const int d  = gw * 4 + (l >> 3);

    const float ald = g_ald2[d];
    float t0 = g_als2[d] + ald;
    float w  = exp2f(fmaxf(t0, 0.2f * t0));
    unsigned long long EWs = packf2(w, w);
    uint4 rs = *(const uint4*)(g_h2h + d * 32 + c * 4);
    unsigned long long a0 = mulf2(h2f2(rs.x), EWs);
    unsigned long long a1 = mulf2(h2f2(rs.y), EWs);
    unsigned long long a2 = mulf2(h2f2(rs.z), EWs);
    unsigned long long a3 = mulf2(h2f2(rs.w), EWs);
    float den = w;

    const int deg = min(g_cnt[d], MAXDEG);
    int m = deg;
    m = max(m, __shfl_xor_sync(0xffffffffu, m, 8));
    m = max(m, __shfl_xor_sync(0xffffffffu, m, 16));
    const int* __restrict__ ell = g_ell + d * MAXDEG;

    for (int e0 = 0; e0 < m; e0 += 4) {
        int4 si = __ldg((const int4*)(ell + e0));
#pragma unroll
        for (int k = 0; k < 4; k++) {
            int s = (k == 0) ? si.x : (k == 1) ? si.y : (k == 2) ? si.z : si.w;
            float as = __ldg(g_als2 + s);
            float tt = as + ald;
            float ew = exp2f(fmaxf(tt, 0.2f * tt));
            unsigned long long EW = packf2(ew, ew);
            uint4 r = __ldg((const uint4*)(g_h2h + s * 32 + c * 4));
            ffma2(a0, h2f2(r.x), EW);
            ffma2(a1, h2f2(r.y), EW);
            ffma2(a2, h2f2(r.z), EW);
            ffma2(a3, h2f2(r.w), EW);
            den += ew;
        }
    }
    float inv = 1.f / den;
    float2 p0 = unpackf2(a0), p1 = unpackf2(a1), p2 = unpackf2(a2), p3 = unpackf2(a3);
    float4 bb0 = __ldg((const float4*)b2 + c * 2);
    float4 bb1 = __ldg((const float4*)b2 + c * 2 + 1);
    float4 r0, r1;
    r0.x = fmaf(p0.x, inv, bb0.x);
    r0.y = fmaf(p0.y, inv, bb0.y);
    r0.z = fmaf(p1.x, inv, bb0.z);
    r0.w = fmaf(p1.y, inv, bb0.w);
    r1.x = fmaf(p2.x, inv, bb1.x);
    r1.y = fmaf(p2.y, inv, bb1.y);
    r1.z = fmaf(p3.x, inv, bb1.z);
    r1.w = fmaf(p3.y, inv, bb1.w);
    *(float4*)(out + d * 64 + c * 8)     = r0;
    *(float4*)(out + d * 64 + c * 8 + 4) = r1;
}

// ---------------- launch ----------------
extern "C" void kernel_launch(void* const* d_in, const int* in_sizes, int n_in,
                              void* d_out, int out_size) {
    const float* x   = (const float*)d_in[0];
    const int*   ei  = (const int*)d_in[1];
    const float* W1  = (const float*)d_in[2];
    const float* as1 = (const float*)d_in[3];
    const float* ad1 = (const float*)d_in[4];
    const float* b1  = (const float*)d_in[5];
    const float* W2  = (const float*)d_in[6];
    const float* as2 = (const float*)d_in[7];
    const float* ad2 = (const float*)d_in[8];
    const float* b2  = (const float*)d_in[9];
    float* out = (float*)d_out;

    const int GB = (NN + 127) / 128;
    const int AGGB = NN / 32;

    zero_cnt_kernel<<<(NN + 255) / 256, 256>>>();
    pad_ell_kernel<<<(NN * (MAXDEG / 4) + 255) / 256, 256>>>();
    build_ell_kernel<<<(EE + 255) / 256, 256>>>(ei);
    gemm1_tc<<<GB, 128>>>(x, W1, as1, ad1);
    agg1_kernel<<<AGGB, 256>>>(b1);
    gemm2_tc<<<GB, 128>>>(W2, as2, ad2);
    agg2_kernel<<<AGGB, 256>>>(b2, out);
}